// round 16
// baseline (speedup 1.0000x reference)
#include <cuda_runtime.h>
#include <cstdint>
#include <cstddef>

#define Ss 2048
#define Dd 512
#define Hh 8
#define DKk 64
#define BH 16
#define MM 4096
#define SCALE 0.125f

#define LDA 36    // proj/pv smem row stride (words)
#define LDS2 68   // scores operand row stride (words)
#define LDST 72   // scores stage row stride (words)

// ---------------- scratch ----------------
__device__ float g_Q[BH * Ss * DKk];     // [b,h,s,dk]
__device__ float g_K[BH * Ss * DKk];     // [b,h,s,dk]
__device__ float g_Vt[BH * DKk * Ss];    // [b,h,dk,s]
__device__ float g_O[MM * Dd];           // merged heads [b,s,d]
__device__ float g_lpart[BH * Ss * 64];
__device__ float g_invl[BH * Ss];

// ---------------- helpers ----------------
__device__ __forceinline__ uint32_t f2tf(float x) {
    uint32_t r;
    asm("cvt.rna.tf32.f32 %0, %1;" : "=r"(r) : "f"(x));
    return r;
}
__device__ __forceinline__ void mma_tf32(float& c0, float& c1, float& c2, float& c3,
                                         uint32_t a0, uint32_t a1, uint32_t a2, uint32_t a3,
                                         uint32_t b0, uint32_t b1) {
    asm volatile(
        "mma.sync.aligned.m16n8k8.row.col.f32.tf32.tf32.f32 "
        "{%0,%1,%2,%3}, {%4,%5,%6,%7}, {%8,%9}, {%0,%1,%2,%3};"
        : "+f"(c0), "+f"(c1), "+f"(c2), "+f"(c3)
        : "r"(a0), "r"(a1), "r"(a2), "r"(a3), "r"(b0), "r"(b1));
}
__device__ __forceinline__ void ldsm4(uint32_t& r0, uint32_t& r1, uint32_t& r2, uint32_t& r3,
                                      uint32_t addr) {
    asm volatile("ldmatrix.sync.aligned.m8n8.x4.shared.b16 {%0,%1,%2,%3}, [%4];"
                 : "=r"(r0), "=r"(r1), "=r"(r2), "=r"(r3) : "r"(addr));
}

// One 32-k chunk (4 k8 steps), LDA-stride layout, 128-row A (proj path).
__device__ __forceinline__ void mma_chunk32(uint32_t sA, uint32_t sB,
                                            float acc[2][4][4],
                                            int warp_m, int warp_n, int lane) {
    const int q = lane >> 3, rr = lane & 7;
    uint32_t aA0 = sA + (((warp_m * 32 + (q & 1) * 8 + rr) * LDA + (q >> 1) * 4) << 2);
    uint32_t aA1 = aA0 + 16 * LDA * 4;
    uint32_t aB0 = sB + (((warp_n * 32 + (q >> 1) * 8 + rr) * LDA + (q & 1) * 4) << 2);
    uint32_t aB1 = aB0 + 16 * LDA * 4;
#pragma unroll
    for (int s = 0; s < 4; s++) {
        uint32_t a[2][4], b[2][4];
        ldsm4(a[0][0], a[0][1], a[0][2], a[0][3], aA0 + s * 32);
        ldsm4(a[1][0], a[1][1], a[1][2], a[1][3], aA1 + s * 32);
        ldsm4(b[0][0], b[0][1], b[0][2], b[0][3], aB0 + s * 32);
        ldsm4(b[1][0], b[1][1], b[1][2], b[1][3], aB1 + s * 32);
#pragma unroll
        for (int t = 0; t < 2; t++)
#pragma unroll
            for (int u = 0; u < 4; u++) {
                float* cc = acc[t][u];
                mma_tf32(cc[0], cc[1], cc[2], cc[3],
                         a[t][0], a[t][1], a[t][2], a[t][3],
                         b[u >> 1][(u & 1) * 2], b[u >> 1][(u & 1) * 2 + 1]);
            }
    }
}

// =====================================================================
// Projection GEMM (unchanged): K=512, tile 128x64.
// =====================================================================
template <int MODE>
__global__ __launch_bounds__(256, 2) void gemm_k(
    const float* __restrict__ A, const float* __restrict__ B,
    float* __restrict__ Out)
{
    const int m0 = blockIdx.y * 128;
    const int n0 = blockIdx.x * 64;
    const int tid = threadIdx.x;
    const int lane = tid & 31, wid = tid >> 5;
    const int warp_m = wid & 3, warp_n = wid >> 2;
    const int g = lane >> 2, tk = lane & 3;

    __shared__ uint32_t As[128 * LDA];
    __shared__ uint32_t Bs[64 * LDA];
    const uint32_t sA = (uint32_t)__cvta_generic_to_shared(As);
    const uint32_t sB = (uint32_t)__cvta_generic_to_shared(Bs);

    float acc[2][4][4];
#pragma unroll
    for (int t = 0; t < 2; t++)
#pragma unroll
        for (int u = 0; u < 4; u++)
#pragma unroll
            for (int j = 0; j < 4; j++) acc[t][u][j] = 0.f;

    float4 pa[4], pb[2];
#pragma unroll
    for (int i = 0; i < 4; i++) {
        int v = tid + 256 * i, row = v >> 3, c4 = v & 7;
        pa[i] = *(const float4*)&A[(size_t)(m0 + row) * Dd + c4 * 4];
    }
#pragma unroll
    for (int i = 0; i < 2; i++) {
        int v = tid + 256 * i, row = v >> 3, c4 = v & 7;
        pb[i] = *(const float4*)&B[(size_t)(n0 + row) * Dd + c4 * 4];
    }

    for (int c = 0; c < 16; c++) {
#pragma unroll
        for (int i = 0; i < 4; i++) {
            int v = tid + 256 * i, row = v >> 3, c4 = v & 7;
            uint32_t* w = &As[row * LDA + c4 * 4];
            w[0] = f2tf(pa[i].x); w[1] = f2tf(pa[i].y);
            w[2] = f2tf(pa[i].z); w[3] = f2tf(pa[i].w);
        }
#pragma unroll
        for (int i = 0; i < 2; i++) {
            int v = tid + 256 * i, row = v >> 3, c4 = v & 7;
            uint32_t* w = &Bs[row * LDA + c4 * 4];
            w[0] = f2tf(pb[i].x); w[1] = f2tf(pb[i].y);
            w[2] = f2tf(pb[i].z); w[3] = f2tf(pb[i].w);
        }
        __syncthreads();
        if (c + 1 < 16) {
            const int k1 = (c + 1) * 32;
#pragma unroll
            for (int i = 0; i < 4; i++) {
                int v = tid + 256 * i, row = v >> 3, c4 = v & 7;
                pa[i] = *(const float4*)&A[(size_t)(m0 + row) * Dd + k1 + c4 * 4];
            }
#pragma unroll
            for (int i = 0; i < 2; i++) {
                int v = tid + 256 * i, row = v >> 3, c4 = v & 7;
                pb[i] = *(const float4*)&B[(size_t)(n0 + row) * Dd + k1 + c4 * 4];
            }
        }
        mma_chunk32(sA, sB, acc, warp_m, warp_n, lane);
        __syncthreads();
    }

#pragma unroll
    for (int t = 0; t < 2; t++) {
#pragma unroll
        for (int half = 0; half < 2; half++) {
            const int m = m0 + warp_m * 32 + t * 16 + half * 8 + g;
#pragma unroll
            for (int u = 0; u < 4; u++) {
                const int n = n0 + warp_n * 32 + u * 8 + tk * 2;
                float v0 = acc[t][u][half * 2 + 0];
                float v1 = acc[t][u][half * 2 + 1];
                if (MODE == 0) {
                    int b = m >> 11, s = m & 2047;
                    int h = n >> 6, dk = n & 63;
                    *(float2*)&Out[(((size_t)(b * Hh + h) * Ss + s) * DKk) + dk] =
                        make_float2(v0, v1);
                } else if (MODE == 1) {
                    int b = m >> 11, s = m & 2047;
                    int h = n >> 6, dk = n & 63;
                    size_t i0 = ((size_t)(b * Hh + h) * DKk + dk) * Ss + s;
                    Out[i0] = v0;
                    Out[i0 + Ss] = v1;
                } else {
                    *(float2*)&Out[(size_t)m * Dd + n] = make_float2(v0, v1);
                }
            }
        }
    }
}

// =====================================================================
// Scores (R13 structure, 3 CTAs/SM): whole-K resident, staged streamout.
// =====================================================================
__global__ __launch_bounds__(256, 3) void scores_kernel(
    const float* __restrict__ Q, const float* __restrict__ Kt,
    float* __restrict__ P, float* __restrict__ lpart)
{
    const int bh = blockIdx.z;
    Q += (size_t)bh * Ss * DKk;
    Kt += (size_t)bh * Ss * DKk;
    P += (size_t)bh * Ss * Ss;

    const int m0 = blockIdx.y * 128;
    const int n0 = blockIdx.x * 64;
    const int tid = threadIdx.x;
    const int lane = tid & 31, wid = tid >> 5;
    const int warp_m = wid & 3, warp_n = wid >> 2;
    const int g = lane >> 2, tk = lane & 3;
    const int q = lane >> 3, rr = lane & 7;

    extern __shared__ uint32_t smem[];
    uint32_t* As = smem;                  // [128][LDS2]
    uint32_t* Bs = smem + 128 * LDS2;     // [64][LDS2]
    const uint32_t sA = (uint32_t)__cvta_generic_to_shared(As);
    const uint32_t sB = (uint32_t)__cvta_generic_to_shared(Bs);

#pragma unroll
    for (int i = 0; i < 8; i++) {
        int v = tid + 256 * i, row = v >> 4, c4 = v & 15;
        float4 x = *(const float4*)&Q[(size_t)(m0 + row) * DKk + c4 * 4];
        uint32_t* w = &As[row * LDS2 + c4 * 4];
        w[0] = f2tf(x.x); w[1] = f2tf(x.y); w[2] = f2tf(x.z); w[3] = f2tf(x.w);
    }
#pragma unroll
    for (int i = 0; i < 4; i++) {
        int v = tid + 256 * i, row = v >> 4, c4 = v & 15;
        float4 x = *(const float4*)&Kt[(size_t)(n0 + row) * DKk + c4 * 4];
        uint32_t* w = &Bs[row * LDS2 + c4 * 4];
        w[0] = f2tf(x.x); w[1] = f2tf(x.y); w[2] = f2tf(x.z); w[3] = f2tf(x.w);
    }
    __syncthreads();

    float acc[2][4][4];
#pragma unroll
    for (int t = 0; t < 2; t++)
#pragma unroll
        for (int u = 0; u < 4; u++)
#pragma unroll
            for (int j = 0; j < 4; j++) acc[t][u][j] = 0.f;

    const uint32_t aA0 = sA + (((warp_m * 32 + (q & 1) * 8 + rr) * LDS2 + (q >> 1) * 4) << 2);
    const uint32_t aA1 = aA0 + 16 * LDS2 * 4;
    const uint32_t aB0 = sB + (((warp_n * 32 + (q >> 1) * 8 + rr) * LDS2 + (q & 1) * 4) << 2);
    const uint32_t aB1 = aB0 + 16 * LDS2 * 4;

#pragma unroll
    for (int c = 0; c < 2; c++) {
        const uint32_t co = c * 128;
#pragma unroll
        for (int s = 0; s < 4; s++) {
            uint32_t a[2][4], b[2][4];
            ldsm4(a[0][0], a[0][1], a[0][2], a[0][3], aA0 + co + s * 32);
            ldsm4(a[1][0], a[1][1], a[1][2], a[1][3], aA1 + co + s * 32);
            ldsm4(b[0][0], b[0][1], b[0][2], b[0][3], aB0 + co + s * 32);
            ldsm4(b[1][0], b[1][1], b[1][2], b[1][3], aB1 + co + s * 32);
#pragma unroll
            for (int t = 0; t < 2; t++)
#pragma unroll
                for (int u = 0; u < 4; u++) {
                    float* cc = acc[t][u];
                    mma_tf32(cc[0], cc[1], cc[2], cc[3],
                             a[t][0], a[t][1], a[t][2], a[t][3],
                             b[u >> 1][(u & 1) * 2], b[u >> 1][(u & 1) * 2 + 1]);
                }
        }
    }
    __syncthreads();

    float* stage = (float*)As;
    float rsumv[2][2];
#pragma unroll
    for (int t = 0; t < 2; t++) {
#pragma unroll
        for (int half = 0; half < 2; half++) {
            const int sr = warp_m * 16 + half * 8 + g;
            float* rowp = stage + sr * LDST + warp_n * 32;
            float rs = 0.f;
#pragma unroll
            for (int u = 0; u < 4; u++) {
                float p0 = __expf(acc[t][u][half * 2 + 0] * SCALE);
                float p1 = __expf(acc[t][u][half * 2 + 1] * SCALE);
                rowp[u * 8 + tk * 2] = p0;
                rowp[u * 8 + tk * 2 + 1] = p1;
                rs += p0 + p1;
            }
            rsumv[t][half] = rs;
        }
        __syncthreads();
#pragma unroll
        for (int i = 0; i < 8; i++) {
            const int sr = wid * 8 + i;
            const int m = m0 + (sr >> 4) * 32 + t * 16 + (sr & 15);
            float2 v = *(float2*)&stage[sr * LDST + lane * 2];
            *(float2*)&P[(size_t)m * Ss + n0 + lane * 2] = v;
        }
        __syncthreads();
    }

#pragma unroll
    for (int t = 0; t < 2; t++)
#pragma unroll
        for (int half = 0; half < 2; half++) {
            float r = rsumv[t][half];
            r += __shfl_xor_sync(0xffffffffu, r, 1);
            r += __shfl_xor_sync(0xffffffffu, r, 2);
            if (tk == 0) {
                const int m = m0 + warp_m * 32 + t * 16 + half * 8 + g;
                lpart[((size_t)(bh * Ss + m)) * 64 + blockIdx.x * 2 + warp_n] = r;
            }
        }
}

// ---------------- reduce partial sums -> 1/l ----------------
__global__ __launch_bounds__(256) void reduce_l(const float* __restrict__ lpart,
                                                float* __restrict__ invl)
{
    int i = blockIdx.x * 256 + threadIdx.x;
    const float* p = lpart + (size_t)i * 64;
    float s = 0.f;
#pragma unroll
    for (int j = 0; j < 64; j++) s += p[j];
    invl[i] = 1.f / s;
}

// =====================================================================
// PV: m-tile 64 (grid 512 blocks), warp tile 16x32, 3 CTAs/SM.
// O = (P~ * invl) @ V, normalized-P writeback. K=2048.
// =====================================================================
__global__ __launch_bounds__(256, 3) void pv_kernel(
    float* __restrict__ P, const float* __restrict__ Vt,
    float* __restrict__ O, const float* __restrict__ invl)
{
    const int bh = blockIdx.z;
    const int b_ = bh >> 3, h_ = bh & 7;
    P += (size_t)bh * Ss * Ss;
    const float* Vb = Vt + (size_t)bh * DKk * Ss;
    const int m0 = blockIdx.y * 64;

    const int tid = threadIdx.x;
    const int lane = tid & 31, wid = tid >> 5;
    const int warp_m = wid & 3, warp_n = wid >> 2;
    const int g = lane >> 2, tk = lane & 3;
    const int q = lane >> 3, rr = lane & 7;

    __shared__ uint32_t As[64 * LDA];
    __shared__ uint32_t Bs[64 * LDA];
    const uint32_t sA = (uint32_t)__cvta_generic_to_shared(As);
    const uint32_t sB = (uint32_t)__cvta_generic_to_shared(Bs);

    float acc[4][4];
#pragma unroll
    for (int u = 0; u < 4; u++)
#pragma unroll
        for (int j = 0; j < 4; j++) acc[u][j] = 0.f;

    int arow[2];
    float inva[2];
#pragma unroll
    for (int i = 0; i < 2; i++) {
        arow[i] = (tid + 256 * i) >> 3;
        inva[i] = invl[bh * Ss + m0 + arow[i]];
    }

    float4 pa[2], pb[2];
#pragma unroll
    for (int i = 0; i < 2; i++) {
        int c4 = (tid + 256 * i) & 7;
        pa[i] = *(const float4*)&P[(size_t)(m0 + arow[i]) * Ss + c4 * 4];
    }
#pragma unroll
    for (int i = 0; i < 2; i++) {
        int v = tid + 256 * i, row = v >> 3, c4 = v & 7;
        pb[i] = *(const float4*)&Vb[(size_t)row * Ss + c4 * 4];
    }

    const uint32_t aA0 = sA + (((warp_m * 16 + (q & 1) * 8 + rr) * LDA + (q >> 1) * 4) << 2);
    const uint32_t aB0 = sB + (((warp_n * 32 + (q >> 1) * 8 + rr) * LDA + (q & 1) * 4) << 2);
    const uint32_t aB1 = aB0 + 16 * LDA * 4;

    for (int c = 0; c < 64; c++) {
        const int k0 = c * 32;
#pragma unroll
        for (int i = 0; i < 2; i++) {
            int c4 = (tid + 256 * i) & 7;
            float f0 = pa[i].x * inva[i], f1 = pa[i].y * inva[i];
            float f2 = pa[i].z * inva[i], f3 = pa[i].w * inva[i];
            *(float4*)&P[(size_t)(m0 + arow[i]) * Ss + k0 + c4 * 4] =
                make_float4(f0, f1, f2, f3);
            uint32_t* w = &As[arow[i] * LDA + c4 * 4];
            w[0] = f2tf(f0); w[1] = f2tf(f1); w[2] = f2tf(f2); w[3] = f2tf(f3);
        }
#pragma unroll
        for (int i = 0; i < 2; i++) {
            int v = tid + 256 * i, row = v >> 3, c4 = v & 7;
            uint32_t* w = &Bs[row * LDA + c4 * 4];
            w[0] = f2tf(pb[i].x); w[1] = f2tf(pb[i].y);
            w[2] = f2tf(pb[i].z); w[3] = f2tf(pb[i].w);
        }
        __syncthreads();

        if (c + 1 < 64) {
            const int k1 = k0 + 32;
#pragma unroll
            for (int i = 0; i < 2; i++) {
                int c4 = (tid + 256 * i) & 7;
                pa[i] = *(const float4*)&P[(size_t)(m0 + arow[i]) * Ss + k1 + c4 * 4];
            }
#pragma unroll
            for (int i = 0; i < 2; i++) {
                int v = tid + 256 * i, row = v >> 3, c4 = v & 7;
                pb[i] = *(const float4*)&Vb[(size_t)row * Ss + k1 + c4 * 4];
            }
        }

#pragma unroll
        for (int s = 0; s < 4; s++) {
            uint32_t a[4], b[2][4];
            ldsm4(a[0], a[1], a[2], a[3], aA0 + s * 32);
            ldsm4(b[0][0], b[0][1], b[0][2], b[0][3], aB0 + s * 32);
            ldsm4(b[1][0], b[1][1], b[1][2], b[1][3], aB1 + s * 32);
#pragma unroll
            for (int u = 0; u < 4; u++) {
                float* cc = acc[u];
                mma_tf32(cc[0], cc[1], cc[2], cc[3],
                         a[0], a[1], a[2], a[3],
                         b[u >> 1][(u & 1) * 2], b[u >> 1][(u & 1) * 2 + 1]);
            }
        }
        __syncthreads();
    }

#pragma unroll
    for (int half = 0; half < 2; half++) {
        const int m = m0 + warp_m * 16 + half * 8 + g;
#pragma unroll
        for (int u = 0; u < 4; u++) {
            const int n = warp_n * 32 + u * 8 + tk * 2;
            *(float2*)&O[((size_t)(b_ * Ss + m)) * Dd + h_ * DKk + n] =
                make_float2(acc[u][half * 2 + 0], acc[u][half * 2 + 1]);
        }
    }
}

// ---------------- launch ----------------
extern "C" void kernel_launch(void* const* d_in, const int* in_sizes, int n_in,
                              void* d_out, int out_size)
{
    const float* query = (const float*)d_in[0];
    const float* key   = (const float*)d_in[1];
    const float* value = (const float*)d_in[2];
    const float* w_q   = (const float*)d_in[3];
    const float* w_k   = (const float*)d_in[4];
    const float* w_v   = (const float*)d_in[5];
    const float* w_o   = (const float*)d_in[6];

    float* out_main = (float*)d_out;
    float* p_attn   = out_main + (size_t)MM * Dd;

    float *Qp, *Kp, *Vp, *Op, *Lp, *Ip;
    cudaGetSymbolAddress((void**)&Qp, g_Q);
    cudaGetSymbolAddress((void**)&Kp, g_K);
    cudaGetSymbolAddress((void**)&Vp, g_Vt);
    cudaGetSymbolAddress((void**)&Op, g_O);
    cudaGetSymbolAddress((void**)&Lp, g_lpart);
    cudaGetSymbolAddress((void**)&Ip, g_invl);

    const int sc_smem = (128 * LDS2 + 64 * LDS2) * 4;   // 52224 B
    static bool attr_done = false;
    if (!attr_done) {
        cudaFuncSetAttribute(scores_kernel,
                             cudaFuncAttributeMaxDynamicSharedMemorySize, sc_smem);
        attr_done = true;
    }

    dim3 pj_grid(Dd / 64, MM / 128);        // (8, 32)
    gemm_k<0><<<pj_grid, 256>>>(query, w_q, Qp);
    gemm_k<0><<<pj_grid, 256>>>(key,   w_k, Kp);
    gemm_k<1><<<pj_grid, 256>>>(value, w_v, Vp);

    dim3 sc_grid(Ss / 64, Ss / 128, BH);    // (32, 16, 16)
    scores_kernel<<<sc_grid, 256, sc_smem>>>(Qp, Kp, p_attn, Lp);

    reduce_l<<<(BH * Ss) / 256, 256>>>(Lp, Ip);

    dim3 pv_grid(1, Ss / 64, BH);           // (1, 32, 16) = 512 blocks
    pv_kernel<<<pv_grid, 256>>>(p_attn, Vp, Op, Ip);

    gemm_k<2><<<pj_grid, 256>>>(Op, w_o, out_main);
}

// round 17
// speedup vs baseline: 1.1279x; 1.1279x over previous
#include <cuda_runtime.h>
#include <cstdint>
#include <cstddef>

#define Ss 2048
#define Dd 512
#define Hh 8
#define DKk 64
#define BH 16
#define MM 4096
#define SCALE 0.125f

#define LDA 36    // proj/pv smem row stride (words)
#define LDS2 68   // scores operand row stride (words)
#define LDST 72   // scores stage row stride (words)

// ---------------- scratch ----------------
__device__ float g_Q[BH * Ss * DKk];     // [b,h,s,dk]
__device__ float g_K[BH * Ss * DKk];     // [b,h,s,dk]
__device__ float g_Vt[BH * DKk * Ss];    // [b,h,dk,s]
__device__ float g_O[MM * Dd];           // merged heads [b,s,d]
__device__ float g_lpart[BH * Ss * 64];
__device__ float g_invl[BH * Ss];

// ---------------- helpers ----------------
__device__ __forceinline__ uint32_t f2tf(float x) {
    uint32_t r;
    asm("cvt.rna.tf32.f32 %0, %1;" : "=r"(r) : "f"(x));
    return r;
}
__device__ __forceinline__ void mma_tf32(float& c0, float& c1, float& c2, float& c3,
                                         uint32_t a0, uint32_t a1, uint32_t a2, uint32_t a3,
                                         uint32_t b0, uint32_t b1) {
    asm volatile(
        "mma.sync.aligned.m16n8k8.row.col.f32.tf32.tf32.f32 "
        "{%0,%1,%2,%3}, {%4,%5,%6,%7}, {%8,%9}, {%0,%1,%2,%3};"
        : "+f"(c0), "+f"(c1), "+f"(c2), "+f"(c3)
        : "r"(a0), "r"(a1), "r"(a2), "r"(a3), "r"(b0), "r"(b1));
}
__device__ __forceinline__ void ldsm4(uint32_t& r0, uint32_t& r1, uint32_t& r2, uint32_t& r3,
                                      uint32_t addr) {
    asm volatile("ldmatrix.sync.aligned.m8n8.x4.shared.b16 {%0,%1,%2,%3}, [%4];"
                 : "=r"(r0), "=r"(r1), "=r"(r2), "=r"(r3) : "r"(addr));
}

// One 32-k chunk (4 k8 steps), LDA-stride layout, 128-row A.
__device__ __forceinline__ void mma_chunk32(uint32_t sA, uint32_t sB,
                                            float acc[2][4][4],
                                            int warp_m, int warp_n, int lane) {
    const int q = lane >> 3, rr = lane & 7;
    uint32_t aA0 = sA + (((warp_m * 32 + (q & 1) * 8 + rr) * LDA + (q >> 1) * 4) << 2);
    uint32_t aA1 = aA0 + 16 * LDA * 4;
    uint32_t aB0 = sB + (((warp_n * 32 + (q >> 1) * 8 + rr) * LDA + (q & 1) * 4) << 2);
    uint32_t aB1 = aB0 + 16 * LDA * 4;
#pragma unroll
    for (int s = 0; s < 4; s++) {
        uint32_t a[2][4], b[2][4];
        ldsm4(a[0][0], a[0][1], a[0][2], a[0][3], aA0 + s * 32);
        ldsm4(a[1][0], a[1][1], a[1][2], a[1][3], aA1 + s * 32);
        ldsm4(b[0][0], b[0][1], b[0][2], b[0][3], aB0 + s * 32);
        ldsm4(b[1][0], b[1][1], b[1][2], b[1][3], aB1 + s * 32);
#pragma unroll
        for (int t = 0; t < 2; t++)
#pragma unroll
            for (int u = 0; u < 4; u++) {
                float* cc = acc[t][u];
                mma_tf32(cc[0], cc[1], cc[2], cc[3],
                         a[t][0], a[t][1], a[t][2], a[t][3],
                         b[u >> 1][(u & 1) * 2], b[u >> 1][(u & 1) * 2 + 1]);
            }
    }
}

// =====================================================================
// Projection GEMM (R11, proven): K=512, tile 128x64.
// =====================================================================
template <int MODE>
__global__ __launch_bounds__(256, 2) void gemm_k(
    const float* __restrict__ A, const float* __restrict__ B,
    float* __restrict__ Out)
{
    const int m0 = blockIdx.y * 128;
    const int n0 = blockIdx.x * 64;
    const int tid = threadIdx.x;
    const int lane = tid & 31, wid = tid >> 5;
    const int warp_m = wid & 3, warp_n = wid >> 2;
    const int g = lane >> 2, tk = lane & 3;

    __shared__ uint32_t As[128 * LDA];
    __shared__ uint32_t Bs[64 * LDA];
    const uint32_t sA = (uint32_t)__cvta_generic_to_shared(As);
    const uint32_t sB = (uint32_t)__cvta_generic_to_shared(Bs);

    float acc[2][4][4];
#pragma unroll
    for (int t = 0; t < 2; t++)
#pragma unroll
        for (int u = 0; u < 4; u++)
#pragma unroll
            for (int j = 0; j < 4; j++) acc[t][u][j] = 0.f;

    float4 pa[4], pb[2];
#pragma unroll
    for (int i = 0; i < 4; i++) {
        int v = tid + 256 * i, row = v >> 3, c4 = v & 7;
        pa[i] = *(const float4*)&A[(size_t)(m0 + row) * Dd + c4 * 4];
    }
#pragma unroll
    for (int i = 0; i < 2; i++) {
        int v = tid + 256 * i, row = v >> 3, c4 = v & 7;
        pb[i] = *(const float4*)&B[(size_t)(n0 + row) * Dd + c4 * 4];
    }

    for (int c = 0; c < 16; c++) {
#pragma unroll
        for (int i = 0; i < 4; i++) {
            int v = tid + 256 * i, row = v >> 3, c4 = v & 7;
            uint32_t* w = &As[row * LDA + c4 * 4];
            w[0] = f2tf(pa[i].x); w[1] = f2tf(pa[i].y);
            w[2] = f2tf(pa[i].z); w[3] = f2tf(pa[i].w);
        }
#pragma unroll
        for (int i = 0; i < 2; i++) {
            int v = tid + 256 * i, row = v >> 3, c4 = v & 7;
            uint32_t* w = &Bs[row * LDA + c4 * 4];
            w[0] = f2tf(pb[i].x); w[1] = f2tf(pb[i].y);
            w[2] = f2tf(pb[i].z); w[3] = f2tf(pb[i].w);
        }
        __syncthreads();
        if (c + 1 < 16) {
            const int k1 = (c + 1) * 32;
#pragma unroll
            for (int i = 0; i < 4; i++) {
                int v = tid + 256 * i, row = v >> 3, c4 = v & 7;
                pa[i] = *(const float4*)&A[(size_t)(m0 + row) * Dd + k1 + c4 * 4];
            }
#pragma unroll
            for (int i = 0; i < 2; i++) {
                int v = tid + 256 * i, row = v >> 3, c4 = v & 7;
                pb[i] = *(const float4*)&B[(size_t)(n0 + row) * Dd + k1 + c4 * 4];
            }
        }
        mma_chunk32(sA, sB, acc, warp_m, warp_n, lane);
        __syncthreads();
    }

#pragma unroll
    for (int t = 0; t < 2; t++) {
#pragma unroll
        for (int half = 0; half < 2; half++) {
            const int m = m0 + warp_m * 32 + t * 16 + half * 8 + g;
#pragma unroll
            for (int u = 0; u < 4; u++) {
                const int n = n0 + warp_n * 32 + u * 8 + tk * 2;
                float v0 = acc[t][u][half * 2 + 0];
                float v1 = acc[t][u][half * 2 + 1];
                if (MODE == 0) {
                    int b = m >> 11, s = m & 2047;
                    int h = n >> 6, dk = n & 63;
                    *(float2*)&Out[(((size_t)(b * Hh + h) * Ss + s) * DKk) + dk] =
                        make_float2(v0, v1);
                } else if (MODE == 1) {
                    int b = m >> 11, s = m & 2047;
                    int h = n >> 6, dk = n & 63;
                    size_t i0 = ((size_t)(b * Hh + h) * DKk + dk) * Ss + s;
                    Out[i0] = v0;
                    Out[i0 + Ss] = v1;
                } else {
                    *(float2*)&Out[(size_t)m * Dd + n] = make_float2(v0, v1);
                }
            }
        }
    }
}

// =====================================================================
// Scores (R16, proven 108.5us): 3 CTAs/SM, whole-K resident, staged streamout.
// =====================================================================
__global__ __launch_bounds__(256, 3) void scores_kernel(
    const float* __restrict__ Q, const float* __restrict__ Kt,
    float* __restrict__ P, float* __restrict__ lpart)
{
    const int bh = blockIdx.z;
    Q += (size_t)bh * Ss * DKk;
    Kt += (size_t)bh * Ss * DKk;
    P += (size_t)bh * Ss * Ss;

    const int m0 = blockIdx.y * 128;
    const int n0 = blockIdx.x * 64;
    const int tid = threadIdx.x;
    const int lane = tid & 31, wid = tid >> 5;
    const int warp_m = wid & 3, warp_n = wid >> 2;
    const int g = lane >> 2, tk = lane & 3;
    const int q = lane >> 3, rr = lane & 7;

    extern __shared__ uint32_t smem[];
    uint32_t* As = smem;                  // [128][LDS2]
    uint32_t* Bs = smem + 128 * LDS2;     // [64][LDS2]
    const uint32_t sA = (uint32_t)__cvta_generic_to_shared(As);
    const uint32_t sB = (uint32_t)__cvta_generic_to_shared(Bs);

#pragma unroll
    for (int i = 0; i < 8; i++) {
        int v = tid + 256 * i, row = v >> 4, c4 = v & 15;
        float4 x = *(const float4*)&Q[(size_t)(m0 + row) * DKk + c4 * 4];
        uint32_t* w = &As[row * LDS2 + c4 * 4];
        w[0] = f2tf(x.x); w[1] = f2tf(x.y); w[2] = f2tf(x.z); w[3] = f2tf(x.w);
    }
#pragma unroll
    for (int i = 0; i < 4; i++) {
        int v = tid + 256 * i, row = v >> 4, c4 = v & 15;
        float4 x = *(const float4*)&Kt[(size_t)(n0 + row) * DKk + c4 * 4];
        uint32_t* w = &Bs[row * LDS2 + c4 * 4];
        w[0] = f2tf(x.x); w[1] = f2tf(x.y); w[2] = f2tf(x.z); w[3] = f2tf(x.w);
    }
    __syncthreads();

    float acc[2][4][4];
#pragma unroll
    for (int t = 0; t < 2; t++)
#pragma unroll
        for (int u = 0; u < 4; u++)
#pragma unroll
            for (int j = 0; j < 4; j++) acc[t][u][j] = 0.f;

    const uint32_t aA0 = sA + (((warp_m * 32 + (q & 1) * 8 + rr) * LDS2 + (q >> 1) * 4) << 2);
    const uint32_t aA1 = aA0 + 16 * LDS2 * 4;
    const uint32_t aB0 = sB + (((warp_n * 32 + (q >> 1) * 8 + rr) * LDS2 + (q & 1) * 4) << 2);
    const uint32_t aB1 = aB0 + 16 * LDS2 * 4;

#pragma unroll
    for (int c = 0; c < 2; c++) {
        const uint32_t co = c * 128;
#pragma unroll
        for (int s = 0; s < 4; s++) {
            uint32_t a[2][4], b[2][4];
            ldsm4(a[0][0], a[0][1], a[0][2], a[0][3], aA0 + co + s * 32);
            ldsm4(a[1][0], a[1][1], a[1][2], a[1][3], aA1 + co + s * 32);
            ldsm4(b[0][0], b[0][1], b[0][2], b[0][3], aB0 + co + s * 32);
            ldsm4(b[1][0], b[1][1], b[1][2], b[1][3], aB1 + co + s * 32);
#pragma unroll
            for (int t = 0; t < 2; t++)
#pragma unroll
                for (int u = 0; u < 4; u++) {
                    float* cc = acc[t][u];
                    mma_tf32(cc[0], cc[1], cc[2], cc[3],
                             a[t][0], a[t][1], a[t][2], a[t][3],
                             b[u >> 1][(u & 1) * 2], b[u >> 1][(u & 1) * 2 + 1]);
                }
        }
    }
    __syncthreads();

    float* stage = (float*)As;
    float rsumv[2][2];
#pragma unroll
    for (int t = 0; t < 2; t++) {
#pragma unroll
        for (int half = 0; half < 2; half++) {
            const int sr = warp_m * 16 + half * 8 + g;
            float* rowp = stage + sr * LDST + warp_n * 32;
            float rs = 0.f;
#pragma unroll
            for (int u = 0; u < 4; u++) {
                float p0 = __expf(acc[t][u][half * 2 + 0] * SCALE);
                float p1 = __expf(acc[t][u][half * 2 + 1] * SCALE);
                rowp[u * 8 + tk * 2] = p0;
                rowp[u * 8 + tk * 2 + 1] = p1;
                rs += p0 + p1;
            }
            rsumv[t][half] = rs;
        }
        __syncthreads();
#pragma unroll
        for (int i = 0; i < 8; i++) {
            const int sr = wid * 8 + i;
            const int m = m0 + (sr >> 4) * 32 + t * 16 + (sr & 15);
            float2 v = *(float2*)&stage[sr * LDST + lane * 2];
            *(float2*)&P[(size_t)m * Ss + n0 + lane * 2] = v;
        }
        __syncthreads();
    }

#pragma unroll
    for (int t = 0; t < 2; t++)
#pragma unroll
        for (int half = 0; half < 2; half++) {
            float r = rsumv[t][half];
            r += __shfl_xor_sync(0xffffffffu, r, 1);
            r += __shfl_xor_sync(0xffffffffu, r, 2);
            if (tk == 0) {
                const int m = m0 + warp_m * 32 + t * 16 + half * 8 + g;
                lpart[((size_t)(bh * Ss + m)) * 64 + blockIdx.x * 2 + warp_n] = r;
            }
        }
}

// ---------------- reduce partial sums -> 1/l ----------------
__global__ __launch_bounds__(256) void reduce_l(const float* __restrict__ lpart,
                                                float* __restrict__ invl)
{
    int i = blockIdx.x * 256 + threadIdx.x;
    const float* p = lpart + (size_t)i * 64;
    float s = 0.f;
#pragma unroll
    for (int j = 0; j < 64; j++) s += p[j];
    invl[i] = 1.f / s;
}

// =====================================================================
// PV (R11/R13, proven ~120us): m-tile 128, O = (P~ * invl) @ V + writeback.
// =====================================================================
__global__ __launch_bounds__(256, 2) void pv_kernel(
    float* __restrict__ P, const float* __restrict__ Vt,
    float* __restrict__ O, const float* __restrict__ invl)
{
    const int bh = blockIdx.z;
    const int b_ = bh >> 3, h_ = bh & 7;
    P += (size_t)bh * Ss * Ss;
    const float* Vb = Vt + (size_t)bh * DKk * Ss;
    const int m0 = blockIdx.y * 128;

    const int tid = threadIdx.x;
    const int lane = tid & 31, wid = tid >> 5;
    const int warp_m = wid & 3, warp_n = wid >> 2;
    const int g = lane >> 2, tk = lane & 3;

    __shared__ uint32_t As[128 * LDA];
    __shared__ uint32_t Bs[64 * LDA];
    const uint32_t sA = (uint32_t)__cvta_generic_to_shared(As);
    const uint32_t sB = (uint32_t)__cvta_generic_to_shared(Bs);

    float acc[2][4][4];
#pragma unroll
    for (int t = 0; t < 2; t++)
#pragma unroll
        for (int u = 0; u < 4; u++)
#pragma unroll
            for (int j = 0; j < 4; j++) acc[t][u][j] = 0.f;

    int arow[4];
    float inva[4];
#pragma unroll
    for (int i = 0; i < 4; i++) {
        arow[i] = (tid + 256 * i) >> 3;
        inva[i] = invl[bh * Ss + m0 + arow[i]];
    }

    float4 pa[4], pb[2];
#pragma unroll
    for (int i = 0; i < 4; i++) {
        int c4 = (tid + 256 * i) & 7;
        pa[i] = *(const float4*)&P[(size_t)(m0 + arow[i]) * Ss + c4 * 4];
    }
#pragma unroll
    for (int i = 0; i < 2; i++) {
        int v = tid + 256 * i, row = v >> 3, c4 = v & 7;
        pb[i] = *(const float4*)&Vb[(size_t)row * Ss + c4 * 4];
    }

    for (int c = 0; c < 64; c++) {
        const int k0 = c * 32;
#pragma unroll
        for (int i = 0; i < 4; i++) {
            int c4 = (tid + 256 * i) & 7;
            float f0 = pa[i].x * inva[i], f1 = pa[i].y * inva[i];
            float f2 = pa[i].z * inva[i], f3 = pa[i].w * inva[i];
            *(float4*)&P[(size_t)(m0 + arow[i]) * Ss + k0 + c4 * 4] =
                make_float4(f0, f1, f2, f3);
            uint32_t* w = &As[arow[i] * LDA + c4 * 4];
            w[0] = f2tf(f0); w[1] = f2tf(f1); w[2] = f2tf(f2); w[3] = f2tf(f3);
        }
#pragma unroll
        for (int i = 0; i < 2; i++) {
            int v = tid + 256 * i, row = v >> 3, c4 = v & 7;
            uint32_t* w = &Bs[row * LDA + c4 * 4];
            w[0] = f2tf(pb[i].x); w[1] = f2tf(pb[i].y);
            w[2] = f2tf(pb[i].z); w[3] = f2tf(pb[i].w);
        }
        __syncthreads();

        if (c + 1 < 64) {
            const int k1 = k0 + 32;
#pragma unroll
            for (int i = 0; i < 4; i++) {
                int c4 = (tid + 256 * i) & 7;
                pa[i] = *(const float4*)&P[(size_t)(m0 + arow[i]) * Ss + k1 + c4 * 4];
            }
#pragma unroll
            for (int i = 0; i < 2; i++) {
                int v = tid + 256 * i, row = v >> 3, c4 = v & 7;
                pb[i] = *(const float4*)&Vb[(size_t)row * Ss + k1 + c4 * 4];
            }
        }

        mma_chunk32(sA, sB, acc, warp_m, warp_n, lane);
        __syncthreads();
    }

#pragma unroll
    for (int t = 0; t < 2; t++) {
#pragma unroll
        for (int half = 0; half < 2; half++) {
            const int m = m0 + warp_m * 32 + t * 16 + half * 8 + g;
#pragma unroll
            for (int u = 0; u < 4; u++) {
                const int n = warp_n * 32 + u * 8 + tk * 2;
                *(float2*)&O[((size_t)(b_ * Ss + m)) * Dd + h_ * DKk + n] =
                    make_float2(acc[t][u][half * 2 + 0], acc[t][u][half * 2 + 1]);
            }
        }
    }
}

// ---------------- launch ----------------
extern "C" void kernel_launch(void* const* d_in, const int* in_sizes, int n_in,
                              void* d_out, int out_size)
{
    const float* query = (const float*)d_in[0];
    const float* key   = (const float*)d_in[1];
    const float* value = (const float*)d_in[2];
    const float* w_q   = (const float*)d_in[3];
    const float* w_k   = (const float*)d_in[4];
    const float* w_v   = (const float*)d_in[5];
    const float* w_o   = (const float*)d_in[6];

    float* out_main = (float*)d_out;
    float* p_attn   = out_main + (size_t)MM * Dd;

    float *Qp, *Kp, *Vp, *Op, *Lp, *Ip;
    cudaGetSymbolAddress((void**)&Qp, g_Q);
    cudaGetSymbolAddress((void**)&Kp, g_K);
    cudaGetSymbolAddress((void**)&Vp, g_Vt);
    cudaGetSymbolAddress((void**)&Op, g_O);
    cudaGetSymbolAddress((void**)&Lp, g_lpart);
    cudaGetSymbolAddress((void**)&Ip, g_invl);

    const int sc_smem = (128 * LDS2 + 64 * LDS2) * 4;   // 52224 B
    static bool attr_done = false;
    if (!attr_done) {
        cudaFuncSetAttribute(scores_kernel,
                             cudaFuncAttributeMaxDynamicSharedMemorySize, sc_smem);
        attr_done = true;
    }

    dim3 pj_grid(Dd / 64, MM / 128);        // (8, 32)
    gemm_k<0><<<pj_grid, 256>>>(query, w_q, Qp);
    gemm_k<0><<<pj_grid, 256>>>(key,   w_k, Kp);
    gemm_k<1><<<pj_grid, 256>>>(value, w_v, Vp);

    dim3 sc_grid(Ss / 64, Ss / 128, BH);    // (32, 16, 16)
    scores_kernel<<<sc_grid, 256, sc_smem>>>(Qp, Kp, p_attn, Lp);

    reduce_l<<<(BH * Ss) / 256, 256>>>(Lp, Ip);

    dim3 pv_grid(1, Ss / 128, BH);          // (1, 16, 16) = 256 blocks
    pv_kernel<<<pv_grid, 256>>>(p_attn, Vp, Op, Ip);

    gemm_k<2><<<pj_grid, 256>>>(Op, w_o, out_main);
}